// round 4
// baseline (speedup 1.0000x reference)
#include <cuda_runtime.h>
#include <cuda_fp16.h>
#include <cstdint>

#define NN 4096
#define DD 64
#define NITER 50
#define REGI 10.0f
#define INV_REG 0.1f
#define EPSF 1e-16f
#define AB (1.0f / 4096.0f)
#define INV_SCALE (1.0f / 262144.0f)   // 2^-18
#define LN_SCALE 12.476649250079f      // 18*ln2
#define NBLK 128
#define NTHR 1024
#define DSM_BYTES 66560

// ---------------- persistent device state (no cudaMalloc allowed) ----------
__device__ uint4 g_E4[(size_t)NN * NN / 8];   // E*2^18 in fp16, 32 MiB
__device__ float g_xT[DD * NN];               // x transposed [k][i]
__device__ float g_yT[DD * NN];               // y transposed [k][j]
__device__ float g_xs[NN], g_ys[NN];
__device__ float g_su[NN], g_sv[NN];
__device__ float g_part[NBLK];
__device__ unsigned g_barCount = 0;
__device__ unsigned g_barGen = 0;

extern __shared__ float dsm[];

// ---------------- software grid barrier (128 co-resident CTAs) -------------
__device__ __forceinline__ void gsync(unsigned& gen) {
    __syncthreads();
    if (threadIdx.x == 0) {
        __threadfence();
        if (atomicAdd(&g_barCount, 1u) == NBLK - 1u) {
            atomicExch(&g_barCount, 0u);
            __threadfence();
            atomicAdd(&g_barGen, 1u);
        } else {
            while (*(volatile unsigned*)&g_barGen == gen) { }
        }
        __threadfence();
    }
    gen++;
    __syncthreads();
}

__global__ __launch_bounds__(NTHR, 1) void k_persist(const float* __restrict__ x,
                                                     const float* __restrict__ y,
                                                     float* __restrict__ out) {
    const int tid = threadIdx.x;
    const int b = blockIdx.x;
    const int w = tid >> 5, l = tid & 31;
    unsigned gen = *(volatile unsigned*)&g_barGen;

    // ================= phase 0: norms, su init, transposes =================
    {
        const int row = b * 32 + w;
        float2 vx = *(const float2*)(x + (size_t)row * DD + 2 * l);
        float sx = vx.x * vx.x + vx.y * vx.y;
#pragma unroll
        for (int o = 16; o; o >>= 1) sx += __shfl_xor_sync(~0u, sx, o);
        float2 vy = *(const float2*)(y + (size_t)row * DD + 2 * l);
        float sy = vy.x * vy.x + vy.y * vy.y;
#pragma unroll
        for (int o = 16; o; o >>= 1) sy += __shfl_xor_sync(~0u, sy, o);
        if (l == 0) { g_xs[row] = sx; g_ys[row] = sy; }
        if (w == 0) g_su[b * 32 + l] = AB;
    }
    {
        float* s = dsm;   // [32][65]
        for (int i = tid; i < 32 * 64; i += NTHR) {
            int r = i >> 6, k = i & 63;
            s[r * 65 + k] = x[(size_t)(b * 32 + r) * DD + k];
        }
        __syncthreads();
        for (int i = tid; i < 32 * 64; i += NTHR) {
            int k = i >> 5, c = i & 31;
            g_xT[(size_t)k * NN + b * 32 + c] = s[c * 65 + k];
        }
        __syncthreads();
        for (int i = tid; i < 32 * 64; i += NTHR) {
            int r = i >> 6, k = i & 63;
            s[r * 65 + k] = y[(size_t)(b * 32 + r) * DD + k];
        }
        __syncthreads();
        for (int i = tid; i < 32 * 64; i += NTHR) {
            int k = i >> 5, c = i & 31;
            g_yT[(size_t)k * NN + b * 32 + c] = s[c * 65 + k];
        }
    }
    gsync(gen);

    // ================= phase 1: build E (1024 tiles of 128x128) ============
    {
        float* Xs = dsm;              // [64][128]
        float* Ys = dsm + 64 * 128;   // [64][128]
        const int tx = tid & 31, ty = tid >> 5;
        for (int tt = 0; tt < 8; tt++) {
            const int id = b + tt * NBLK;
            const int i0 = (id >> 5) * 128, j0 = (id & 31) * 128;
            {
                const int k = tid >> 4, rb = (tid & 15) * 8;
                const float4* px = (const float4*)(g_xT + (size_t)k * NN + i0 + rb);
                const float4* py = (const float4*)(g_yT + (size_t)k * NN + j0 + rb);
                *(float4*)&Xs[k * 128 + rb]     = px[0];
                *(float4*)&Xs[k * 128 + rb + 4] = px[1];
                *(float4*)&Ys[k * 128 + rb]     = py[0];
                *(float4*)&Ys[k * 128 + rb + 4] = py[1];
            }
            __syncthreads();
            float acc[4][4] = {};
#pragma unroll 8
            for (int k = 0; k < 64; k++) {
                float4 a4 = *(const float4*)&Xs[k * 128 + ty * 4];
                float4 b4 = *(const float4*)&Ys[k * 128 + tx * 4];
                float ar[4] = {a4.x, a4.y, a4.z, a4.w};
                float br[4] = {b4.x, b4.y, b4.z, b4.w};
#pragma unroll
                for (int r = 0; r < 4; r++)
#pragma unroll
                    for (int c = 0; c < 4; c++) acc[r][c] += ar[r] * br[c];
            }
            float xr[4], yc[4];
#pragma unroll
            for (int r = 0; r < 4; r++) xr[r] = __ldcg(&g_xs[i0 + ty * 4 + r]);
#pragma unroll
            for (int c = 0; c < 4; c++) yc[c] = __ldcg(&g_ys[j0 + tx * 4 + c]);
            __half* Eh = (__half*)g_E4;
#pragma unroll
            for (int r = 0; r < 4; r++) {
                float e0 = __expf((2.f * acc[r][0] - xr[r] - yc[0]) * INV_REG + LN_SCALE);
                float e1 = __expf((2.f * acc[r][1] - xr[r] - yc[1]) * INV_REG + LN_SCALE);
                float e2 = __expf((2.f * acc[r][2] - xr[r] - yc[2]) * INV_REG + LN_SCALE);
                float e3 = __expf((2.f * acc[r][3] - xr[r] - yc[3]) * INV_REG + LN_SCALE);
                union { uint2 u; __half2 h[2]; } pk;
                pk.h[0] = __floats2half2_rn(e0, e1);
                pk.h[1] = __floats2half2_rn(e2, e3);
                *(uint2*)(Eh + (size_t)(i0 + ty * 4 + r) * NN + j0 + tx * 4) = pk.u;
            }
            __syncthreads();
        }
    }
    gsync(gen);

    // ================= phase 2: 50 Sinkhorn iterations =====================
    for (int it = 0; it < NITER; it++) {
        const bool last = (it == NITER - 1);
        // ---- col pass: block owns columns [32b, 32b+32)
        {
            float* sus = dsm;                          // [4096]
            float2* wred = (float2*)(dsm + 4096);      // [32][16]
            {
                float4 v = __ldcg((const float4*)g_su + tid);
                *(float4*)&sus[tid * 4] = v;
            }
            __syncthreads();
            const int c2 = tid & 15, rs = tid >> 4;    // 16 half2-cols x 64 rows in flight
            const __half2* ep = (const __half2*)g_E4 + (size_t)rs * (NN / 2) + b * 16 + c2;
            float ax = 0.f, ay = 0.f;
#pragma unroll 4
            for (int ri = 0; ri < 64; ri++) {
                float2 ef = __half22float2(ep[(size_t)ri * 64 * (NN / 2)]);
                float s = sus[rs + ri * 64];
                ax += ef.x * s;
                ay += ef.y * s;
            }
            ax += __shfl_xor_sync(~0u, ax, 16);        // fold rs-pair within warp
            ay += __shfl_xor_sync(~0u, ay, 16);
            if (l < 16) wred[w * 16 + c2] = make_float2(ax, ay);
            __syncthreads();
            if (tid < 16) {
                float sx = 0.f, sy = 0.f;
#pragma unroll
                for (int q = 0; q < 32; q++) { float2 t2 = wred[q * 16 + tid]; sx += t2.x; sy += t2.y; }
                g_sv[b * 32 + 2 * tid]     = AB / (sx * INV_SCALE + EPSF);
                g_sv[b * 32 + 2 * tid + 1] = AB / (sy * INV_SCALE + EPSF);
            }
        }
        gsync(gen);
        // ---- row pass: block owns rows [32b, 32b+32); loss folded on last it
        {
            __half2* ssv = (__half2*)dsm;              // [2048]
            float* wloss = dsm + 4096;
            {
                float4 v = __ldcg((const float4*)g_sv + tid);
                ssv[2 * tid]     = __floats2half2_rn(v.x, v.y);
                ssv[2 * tid + 1] = __floats2half2_rn(v.z, v.w);
            }
            __syncthreads();
            const int row = b * 32 + w;
            const uint4* ep = g_E4 + (size_t)row * (NN / 8) + l;
            const uint4* sp = (const uint4*)ssv + l;
            float acc = 0.f, accL = 0.f;
#pragma unroll 4
            for (int h = 0; h < 4; h++) {
                uint4 ev[4], vv[4];
#pragma unroll
                for (int q = 0; q < 4; q++) { ev[q] = ep[(h * 4 + q) * 32]; vv[q] = sp[(h * 4 + q) * 32]; }
#pragma unroll
                for (int q = 0; q < 4; q++) {
                    const __half2* eh = (const __half2*)&ev[q];
                    const __half2* vh = (const __half2*)&vv[q];
#pragma unroll
                    for (int k = 0; k < 4; k++) {
                        float2 e = __half22float2(eh[k]);
                        float2 v = __half22float2(vh[k]);
                        acc += e.x * v.x + e.y * v.y;
                        if (last) {
                            float t0 = (e.x > 0.f) ? e.x * (LN_SCALE - __logf(e.x)) : 0.f;
                            float t1 = (e.y > 0.f) ? e.y * (LN_SCALE - __logf(e.y)) : 0.f;
                            accL += t0 * v.x + t1 * v.y;
                        }
                    }
                }
            }
#pragma unroll
            for (int o = 16; o; o >>= 1) acc += __shfl_xor_sync(~0u, acc, o);
            if (last) {
#pragma unroll
                for (int o = 16; o; o >>= 1) accL += __shfl_xor_sync(~0u, accL, o);
            }
            if (l == 0) {
                float su = AB / (acc * INV_SCALE + EPSF);
                g_su[row] = su;
                if (last) wloss[w] = su * accL;
            }
            if (last) {
                __syncthreads();
                if (w == 0) {
                    float v = wloss[l];
#pragma unroll
                    for (int o = 16; o; o >>= 1) v += __shfl_xor_sync(~0u, v, o);
                    if (l == 0) g_part[b] = REGI * INV_SCALE * v;
                }
            }
        }
        gsync(gen);
    }

    // ================= phase 3: final reduction (block 0) ==================
    if (b == 0) {
        float v = (tid < NBLK) ? __ldcg(&g_part[tid]) : 0.f;
#pragma unroll
        for (int o = 16; o; o >>= 1) v += __shfl_xor_sync(~0u, v, o);
        float* fs = dsm;
        if (l == 0) fs[w] = v;
        __syncthreads();
        if (tid == 0) {
            float s = 0.f;
#pragma unroll
            for (int q = 0; q < 32; q++) s += fs[q];
            out[0] = s;
        }
    }
}

// ---------------------------------------------------------------------------
extern "C" void kernel_launch(void* const* d_in, const int* in_sizes, int n_in,
                              void* d_out, int out_size) {
    const float* x = (const float*)d_in[0];
    const float* y = (const float*)d_in[1];
    float* out = (float*)d_out;

    cudaFuncSetAttribute(k_persist, cudaFuncAttributeMaxDynamicSharedMemorySize, DSM_BYTES);
    k_persist<<<NBLK, NTHR, DSM_BYTES>>>(x, y, out);
}

// round 5
// speedup vs baseline: 1.0374x; 1.0374x over previous
#include <cuda_runtime.h>
#include <cuda_fp16.h>
#include <cstdint>

#define NN 4096
#define DD 64
#define NITER 50
#define REGI 10.0f
#define INV_REG 0.1f
#define EPSF 1e-16f
#define AB (1.0f / 4096.0f)
#define INV_SCALE (1.0f / 262144.0f)   // 2^-18
#define LN_SCALE 12.476649250079f      // 18*ln2
#define NBLK 128
#define NTHR 1024
#define DSM_BYTES 66560

// ---------------- persistent device state (no cudaMalloc allowed) ----------
__device__ uint4 g_E4[(size_t)NN * NN / 8];   // E*2^18 in fp16, 32 MiB
__device__ float g_xT[DD * NN];
__device__ float g_yT[DD * NN];
__device__ __align__(16) float g_xs[NN], g_ys[NN];
__device__ __align__(16) float g_su[NN], g_sv[NN];
__device__ float g_part[NBLK];
__device__ unsigned g_barCount = 0;
__device__ unsigned g_barGen = 0;

extern __shared__ float dsm[];

// ---------------- software grid barrier (128 co-resident CTAs) -------------
__device__ __forceinline__ void gsync(unsigned& gen) {
    __syncthreads();
    if (threadIdx.x == 0) {
        __threadfence();
        if (atomicAdd(&g_barCount, 1u) == NBLK - 1u) {
            atomicExch(&g_barCount, 0u);
            __threadfence();
            atomicAdd(&g_barGen, 1u);
        } else {
            while (*(volatile unsigned*)&g_barGen == gen) { }
        }
        __threadfence();
    }
    gen++;
    __syncthreads();
}

__global__ __launch_bounds__(NTHR, 1) void k_persist(const float* __restrict__ x,
                                                     const float* __restrict__ y,
                                                     float* __restrict__ out) {
    const int tid = threadIdx.x;
    const int b = blockIdx.x;
    const int w = tid >> 5, l = tid & 31;
    unsigned gen = *(volatile unsigned*)&g_barGen;

    // ================= phase 0: norms, su init, transposes =================
    {
        const int row = b * 32 + w;
        float2 vx = *(const float2*)(x + (size_t)row * DD + 2 * l);
        float sx = vx.x * vx.x + vx.y * vx.y;
#pragma unroll
        for (int o = 16; o; o >>= 1) sx += __shfl_xor_sync(~0u, sx, o);
        float2 vy = *(const float2*)(y + (size_t)row * DD + 2 * l);
        float sy = vy.x * vy.x + vy.y * vy.y;
#pragma unroll
        for (int o = 16; o; o >>= 1) sy += __shfl_xor_sync(~0u, sy, o);
        if (l == 0) { g_xs[row] = sx; g_ys[row] = sy; }
        if (w == 0) g_su[b * 32 + l] = AB;
    }
    {
        float* s = dsm;   // [32][65]
        for (int i = tid; i < 32 * 64; i += NTHR) {
            int r = i >> 6, k = i & 63;
            s[r * 65 + k] = x[(size_t)(b * 32 + r) * DD + k];
        }
        __syncthreads();
        for (int i = tid; i < 32 * 64; i += NTHR) {
            int k = i >> 5, c = i & 31;
            g_xT[(size_t)k * NN + b * 32 + c] = s[c * 65 + k];
        }
        __syncthreads();
        for (int i = tid; i < 32 * 64; i += NTHR) {
            int r = i >> 6, k = i & 63;
            s[r * 65 + k] = y[(size_t)(b * 32 + r) * DD + k];
        }
        __syncthreads();
        for (int i = tid; i < 32 * 64; i += NTHR) {
            int k = i >> 5, c = i & 31;
            g_yT[(size_t)k * NN + b * 32 + c] = s[c * 65 + k];
        }
    }
    gsync(gen);

    // ================= phase 1: build E (1024 tiles of 128x128) ============
    {
        float* Xs = dsm;              // [64][128]
        float* Ys = dsm + 64 * 128;   // [64][128]
        const int tx = tid & 31, ty = tid >> 5;
        for (int tt = 0; tt < 8; tt++) {
            const int id = b + tt * NBLK;
            const int i0 = (id >> 5) * 128, j0 = (id & 31) * 128;
            {
                const int k = tid >> 4, rb = (tid & 15) * 8;
                const float4* px = (const float4*)(g_xT + (size_t)k * NN + i0 + rb);
                const float4* py = (const float4*)(g_yT + (size_t)k * NN + j0 + rb);
                *(float4*)&Xs[k * 128 + rb]     = px[0];
                *(float4*)&Xs[k * 128 + rb + 4] = px[1];
                *(float4*)&Ys[k * 128 + rb]     = py[0];
                *(float4*)&Ys[k * 128 + rb + 4] = py[1];
            }
            __syncthreads();
            float acc[4][4] = {};
#pragma unroll 8
            for (int k = 0; k < 64; k++) {
                float4 a4 = *(const float4*)&Xs[k * 128 + ty * 4];
                float4 b4 = *(const float4*)&Ys[k * 128 + tx * 4];
                float ar[4] = {a4.x, a4.y, a4.z, a4.w};
                float br[4] = {b4.x, b4.y, b4.z, b4.w};
#pragma unroll
                for (int r = 0; r < 4; r++)
#pragma unroll
                    for (int c = 0; c < 4; c++) acc[r][c] += ar[r] * br[c];
            }
            float xr[4], yc[4];
#pragma unroll
            for (int r = 0; r < 4; r++) xr[r] = __ldcg(&g_xs[i0 + ty * 4 + r]);
#pragma unroll
            for (int c = 0; c < 4; c++) yc[c] = __ldcg(&g_ys[j0 + tx * 4 + c]);
            __half* Eh = (__half*)g_E4;
#pragma unroll
            for (int r = 0; r < 4; r++) {
                float e0 = __expf((2.f * acc[r][0] - xr[r] - yc[0]) * INV_REG + LN_SCALE);
                float e1 = __expf((2.f * acc[r][1] - xr[r] - yc[1]) * INV_REG + LN_SCALE);
                float e2 = __expf((2.f * acc[r][2] - xr[r] - yc[2]) * INV_REG + LN_SCALE);
                float e3 = __expf((2.f * acc[r][3] - xr[r] - yc[3]) * INV_REG + LN_SCALE);
                union { uint2 u; __half2 h[2]; } pk;
                pk.h[0] = __floats2half2_rn(e0, e1);
                pk.h[1] = __floats2half2_rn(e2, e3);
                *(uint2*)(Eh + (size_t)(i0 + ty * 4 + r) * NN + j0 + tx * 4) = pk.u;
            }
            __syncthreads();
        }
    }
    gsync(gen);

    const __half* Eh = (const __half*)g_E4;

    // ================= phase 2: 50 Sinkhorn iterations =====================
    for (int it = 0; it < NITER; it++) {
        // ---- col pass: block owns columns [32b, 32b+32)
        {
            float* ssu = dsm;                      // [4096] fp32
            float* cred = dsm + 4096;              // [32][36]
            {
                float4 v = __ldcg((const float4*)g_su + tid);
                *(float4*)&ssu[tid * 4] = v;
            }
            __syncthreads();
            const int l8 = l & 7, ro = l >> 3;
            // lane handles cols [b*32 + l8*4, +4), rows {st*128 + w*4 + ro}
            const uint2* ep = (const uint2*)Eh + (size_t)(w * 4 + ro) * (NN / 4)
                              + b * 8 + l8;
            const float* sup = ssu + w * 4 + ro;
            float a0 = 0.f, a1 = 0.f, a2 = 0.f, a3 = 0.f;
#pragma unroll 8
            for (int st = 0; st < 32; st++) {
                uint2 ev = ep[(size_t)st * 128 * (NN / 4)];
                float s = sup[st * 128];
                float2 e01 = __half22float2(*(const __half2*)&ev.x);
                float2 e23 = __half22float2(*(const __half2*)&ev.y);
                a0 += e01.x * s;
                a1 += e01.y * s;
                a2 += e23.x * s;
                a3 += e23.y * s;
            }
            // reduce over ro (bits 3,4 of lane)
            a0 += __shfl_xor_sync(~0u, a0, 8);  a0 += __shfl_xor_sync(~0u, a0, 16);
            a1 += __shfl_xor_sync(~0u, a1, 8);  a1 += __shfl_xor_sync(~0u, a1, 16);
            a2 += __shfl_xor_sync(~0u, a2, 8);  a2 += __shfl_xor_sync(~0u, a2, 16);
            a3 += __shfl_xor_sync(~0u, a3, 8);  a3 += __shfl_xor_sync(~0u, a3, 16);
            if (l < 8) *(float4*)&cred[w * 36 + l8 * 4] = make_float4(a0, a1, a2, a3);
            __syncthreads();
            if (tid < 32) {
                float s = 0.f;
#pragma unroll 8
                for (int q = 0; q < 32; q++) s += cred[q * 36 + tid];
                g_sv[b * 32 + tid] = AB / (s * INV_SCALE + EPSF);
            }
        }
        gsync(gen);
        // ---- row pass: block owns rows [32b, 32b+32)
        {
            float* ssv = dsm;                      // [4096] fp32
            float* red = dsm + 4096;               // [32][8]
            {
                float4 v = __ldcg((const float4*)g_sv + tid);
                *(float4*)&ssv[tid * 4] = v;
            }
            __syncthreads();
            const int cs = w & 7, rg = w >> 3;
            const int row0 = b * 32 + rg * 8;
            float acc[8] = {};
#pragma unroll
            for (int u = 0; u < 4; u++) {
                const int colbase = cs * 512 + u * 128 + l * 4;
                float4 vv = *(const float4*)&ssv[colbase];
                uint2 ev[8];
                const __half* eb = Eh + (size_t)row0 * NN + colbase;
#pragma unroll
                for (int r = 0; r < 8; r++)
                    ev[r] = *(const uint2*)(eb + (size_t)r * NN);
#pragma unroll
                for (int r = 0; r < 8; r++) {
                    float2 e01 = __half22float2(*(const __half2*)&ev[r].x);
                    float2 e23 = __half22float2(*(const __half2*)&ev[r].y);
                    acc[r] += e01.x * vv.x + e01.y * vv.y + e23.x * vv.z + e23.y * vv.w;
                }
            }
#pragma unroll
            for (int r = 0; r < 8; r++) {
                float v = acc[r];
#pragma unroll
                for (int o = 16; o; o >>= 1) v += __shfl_xor_sync(~0u, v, o);
                if (l == 0) red[(rg * 8 + r) * 8 + cs] = v;
            }
            __syncthreads();
            if (tid < 32) {
                float s = 0.f;
#pragma unroll
                for (int q = 0; q < 8; q++) s += red[tid * 8 + q];
                g_su[b * 32 + tid] = AB / (s * INV_SCALE + EPSF);
            }
        }
        gsync(gen);
    }

    // ================= phase 2b: loss sweep (rows of this block) ===========
    {
        float* ssv = dsm;
        float* red = dsm + 4096;
        {
            float4 v = __ldcg((const float4*)g_sv + tid);
            *(float4*)&ssv[tid * 4] = v;
        }
        __syncthreads();
        const int cs = w & 7, rg = w >> 3;
        const int row0 = b * 32 + rg * 8;
        float acc[8] = {};
#pragma unroll 1
        for (int u = 0; u < 4; u++) {
            const int colbase = cs * 512 + u * 128 + l * 4;
            float4 vv = *(const float4*)&ssv[colbase];
            const __half* eb = Eh + (size_t)row0 * NN + colbase;
#pragma unroll
            for (int r = 0; r < 8; r++) {
                uint2 evr = *(const uint2*)(eb + (size_t)r * NN);
                float2 e01 = __half22float2(*(const __half2*)&evr.x);
                float2 e23 = __half22float2(*(const __half2*)&evr.y);
                float t0 = (e01.x > 0.f) ? e01.x * (LN_SCALE - __logf(e01.x)) : 0.f;
                float t1 = (e01.y > 0.f) ? e01.y * (LN_SCALE - __logf(e01.y)) : 0.f;
                float t2 = (e23.x > 0.f) ? e23.x * (LN_SCALE - __logf(e23.x)) : 0.f;
                float t3 = (e23.y > 0.f) ? e23.y * (LN_SCALE - __logf(e23.y)) : 0.f;
                acc[r] += t0 * vv.x + t1 * vv.y + t2 * vv.z + t3 * vv.w;
            }
        }
#pragma unroll
        for (int r = 0; r < 8; r++) {
            float v = acc[r];
#pragma unroll
            for (int o = 16; o; o >>= 1) v += __shfl_xor_sync(~0u, v, o);
            if (l == 0) red[(rg * 8 + r) * 8 + cs] = v;
        }
        __syncthreads();
        if (tid < 32) {
            float s = 0.f;
#pragma unroll
            for (int q = 0; q < 8; q++) s += red[tid * 8 + q];
            float t = g_su[b * 32 + tid] * s;    // written by this block
#pragma unroll
            for (int o = 16; o; o >>= 1) t += __shfl_xor_sync(~0u, t, o);
            if (tid == 0) g_part[b] = REGI * INV_SCALE * t;
        }
    }
    gsync(gen);

    // ================= phase 3: final reduction (block 0) ==================
    if (b == 0 && w == 0) {
        float s = 0.f;
#pragma unroll
        for (int q = 0; q < 4; q++) s += __ldcg(&g_part[q * 32 + l]);
#pragma unroll
        for (int o = 16; o; o >>= 1) s += __shfl_xor_sync(~0u, s, o);
        if (l == 0) out[0] = s;
    }
}

// ---------------------------------------------------------------------------
extern "C" void kernel_launch(void* const* d_in, const int* in_sizes, int n_in,
                              void* d_out, int out_size) {
    const float* x = (const float*)d_in[0];
    const float* y = (const float*)d_in[1];
    float* out = (float*)d_out;

    cudaFuncSetAttribute(k_persist, cudaFuncAttributeMaxDynamicSharedMemorySize, DSM_BYTES);
    k_persist<<<NBLK, NTHR, DSM_BYTES>>>(x, y, out);
}